// round 3
// baseline (speedup 1.0000x reference)
#include <cuda_runtime.h>

#define NN 50000
#define EPMAX 850000
#define NEG_SLOPE 0.2f

// ---------------- scratch (device globals; no allocation allowed) ----------------
__device__ __align__(16) float    g_z0[NN * 128];   // layer0 projected features
__device__ __align__(16) float    g_h0[NN * 128];   // layer0 agg/out (acc then elu)
__device__ __align__(16) float    g_z1[NN * 40];    // layer1 projected features
__device__ __align__(16) float    g_el[NN * 4];     // attn left  (layer1 reuses [0,NN))
__device__ __align__(16) float    g_er[NN * 4];     // attn right
__device__ __align__(16) unsigned g_m[NN * 4];      // segment max (encoded)
__device__ __align__(16) float    g_s[NN * 4];      // segment sum
__device__ __align__(16) float    g_e[EPMAX * 4];   // per-edge logits -> exp values

// order-preserving float <-> uint encoding for atomicMax on floats
__device__ __forceinline__ unsigned enc_f(float f) {
    unsigned u = __float_as_uint(f);
    return (u & 0x80000000u) ? ~u : (u | 0x80000000u);
}
__device__ __forceinline__ float dec_f(unsigned u) {
    return (u & 0x80000000u) ? __uint_as_float(u & 0x7fffffffu)
                             : __uint_as_float(~u);
}

// ---------------- GEMM body: C[nrows,M] = A[nrows,K] @ B[K,M] ----------------
// Called only from __global__ wrappers that bind device-global scratch pointers
// in DEVICE code (host code must never take the address of a __device__ symbol).
template <int K, int M, int BM, int BK, int TM, int TN>
__device__ __forceinline__ void gemm_body(const float* __restrict__ A,
                                          const float* __restrict__ B,
                                          float* __restrict__ C, int nrows) {
    constexpr int TX = M / TN;     // threads along columns
    constexpr int TY = BM / TM;    // threads along rows
    constexpr int NT = TX * TY;
    __shared__ float As[BM][BK + 1];
    __shared__ float Bs[BK][M];

    const int tid = threadIdx.x;
    const int tx = tid % TX, ty = tid / TX;
    const int rowBase = blockIdx.x * BM;

    float acc[TM][TN];
#pragma unroll
    for (int i = 0; i < TM; i++)
#pragma unroll
        for (int j = 0; j < TN; j++) acc[i][j] = 0.f;

    for (int k0 = 0; k0 < K; k0 += BK) {
        for (int idx = tid; idx < BM * BK; idx += NT) {
            int r = idx / BK, kk = idx % BK;
            int gr = rowBase + r;
            As[r][kk] = (gr < nrows) ? A[gr * K + k0 + kk] : 0.f;
        }
        for (int idx = tid; idx < BK * M; idx += NT) {
            int kk = idx / M, c = idx % M;
            Bs[kk][c] = B[(k0 + kk) * M + c];
        }
        __syncthreads();
#pragma unroll
        for (int kk = 0; kk < BK; kk++) {
            float a[TM], b[TN];
#pragma unroll
            for (int i = 0; i < TM; i++) a[i] = As[ty * TM + i][kk];
#pragma unroll
            for (int j = 0; j < TN; j++) b[j] = Bs[kk][tx + j * TX];
#pragma unroll
            for (int i = 0; i < TM; i++)
#pragma unroll
                for (int j = 0; j < TN; j++) acc[i][j] = fmaf(a[i], b[j], acc[i][j]);
        }
        __syncthreads();
    }
#pragma unroll
    for (int i = 0; i < TM; i++) {
        int gr = rowBase + ty * TM + i;
        if (gr < nrows) {
#pragma unroll
            for (int j = 0; j < TN; j++) C[gr * M + tx + j * TX] = acc[i][j];
        }
    }
}

__global__ void gemm0_kernel(const float* __restrict__ A, const float* __restrict__ B,
                             int nrows) {
    gemm_body<256, 128, 128, 16, 8, 8>(A, B, g_z0, nrows);
}
__global__ void gemm1_kernel(const float* __restrict__ B, int nrows) {
    gemm_body<128, 40, 128, 16, 8, 5>(g_h0, B, g_z1, nrows);
}

// ---------------- attention scalars: el[n,h] = z[n,h,:].al[h], er likewise ----------------
template <int H, int F>
__device__ __forceinline__ void attn_body(const float* __restrict__ z,
                                          const float* __restrict__ al,
                                          const float* __restrict__ ar) {
    int t = blockIdx.x * blockDim.x + threadIdx.x;
    if (t >= NN * H) return;
    int n = t / H, h = t % H;
    const float* zp = z + n * (H * F) + h * F;
    float sl = 0.f, sr = 0.f;
#pragma unroll
    for (int f = 0; f < F; f++) {
        float v = zp[f];
        sl = fmaf(v, al[h * F + f], sl);
        sr = fmaf(v, ar[h * F + f], sr);
    }
    g_el[t] = sl;
    g_er[t] = sr;
}
__global__ void attn0_kernel(const float* __restrict__ al, const float* __restrict__ ar) {
    attn_body<4, 32>(g_z0, al, ar);
}
__global__ void attn1_kernel(const float* __restrict__ al, const float* __restrict__ ar) {
    attn_body<1, 40>(g_z1, al, ar);
}

// ---------------- zero-init kernels (re-run every graph replay) ----------------
__global__ void zero0_kernel() {
    int i = blockIdx.x * blockDim.x + threadIdx.x;
    if (i < NN * 128) g_h0[i] = 0.f;
    if (i < NN * 4) { g_m[i] = 0u; g_s[i] = 0.f; }
}
__global__ void zero1_kernel(float* __restrict__ out) {
    int i = blockIdx.x * blockDim.x + threadIdx.x;
    if (i < NN * 40) out[i] = 0.f;
    if (i < NN) { g_m[i] = 0u; g_s[i] = 0.f; }
}

// ---------------- edge pass A: logits + segment max (H=4) ----------------
__global__ void edgeA4_kernel(const int* __restrict__ src, const int* __restrict__ dst, int E) {
    int i = blockIdx.x * blockDim.x + threadIdx.x;
    int EP = E + NN;
    if (i >= EP) return;
    int s, d; bool inv = false;
    if (i < E) { s = src[i]; d = dst[i]; inv = (s == d); }
    else       { s = d = i - E; }
    float4 el4 = *(const float4*)(g_el + s * 4);
    float4 er4 = *(const float4*)(g_er + d * 4);
    float e[4] = {el4.x + er4.x, el4.y + er4.y, el4.z + er4.z, el4.w + er4.w};
    float4 eo;
    if (inv) {
        eo = make_float4(-1e30f, -1e30f, -1e30f, -1e30f);
    } else {
#pragma unroll
        for (int h = 0; h < 4; h++) e[h] = e[h] > 0.f ? e[h] : NEG_SLOPE * e[h];
        eo = make_float4(e[0], e[1], e[2], e[3]);
#pragma unroll
        for (int h = 0; h < 4; h++) atomicMax(&g_m[d * 4 + h], enc_f(e[h]));
    }
    *(float4*)(g_e + i * 4) = eo;
}

// ---------------- edge pass B: exp(e - m) + segment sum (H=4) ----------------
__global__ void edgeB4_kernel(const int* __restrict__ dst, int E) {
    int i = blockIdx.x * blockDim.x + threadIdx.x;
    int EP = E + NN;
    if (i >= EP) return;
    int d = (i < E) ? dst[i] : i - E;
    float4 e4 = *(const float4*)(g_e + i * 4);
    float ex0 = __expf(e4.x - dec_f(g_m[d * 4 + 0]));  // invalid: e = -1e30 -> exp -> 0
    float ex1 = __expf(e4.y - dec_f(g_m[d * 4 + 1]));
    float ex2 = __expf(e4.z - dec_f(g_m[d * 4 + 2]));
    float ex3 = __expf(e4.w - dec_f(g_m[d * 4 + 3]));
    *(float4*)(g_e + i * 4) = make_float4(ex0, ex1, ex2, ex3);
    atomicAdd(&g_s[d * 4 + 0], ex0);
    atomicAdd(&g_s[d * 4 + 1], ex1);
    atomicAdd(&g_s[d * 4 + 2], ex2);
    atomicAdd(&g_s[d * 4 + 3], ex3);
}

// ---------------- edge pass C: scatter messages (warp per edge, H=4, F=32) ----------------
__global__ void edgeC4_kernel(const int* __restrict__ src, const int* __restrict__ dst, int E) {
    int t = blockIdx.x * blockDim.x + threadIdx.x;
    int w = t >> 5, lane = t & 31;
    if (w >= E + NN) return;
    int s, d;
    if (w < E) { s = src[w]; d = dst[w]; if (s == d) return; }
    else       { s = d = w - E; }
#pragma unroll
    for (int j = 0; j < 4; j++) {
        float alpha = __fdividef(g_e[w * 4 + j], g_s[d * 4 + j]);
        float v = g_z0[s * 128 + j * 32 + lane] * alpha;
        atomicAdd(&g_h0[d * 128 + j * 32 + lane], v);
    }
}

// ---------------- finalize layer0: elu(acc + b) ----------------
__global__ void fin0_kernel(const float* __restrict__ b0) {
    int i = blockIdx.x * blockDim.x + threadIdx.x;
    if (i >= NN * 128) return;
    float v = g_h0[i] + b0[i & 127];
    g_h0[i] = v > 0.f ? v : (__expf(v) - 1.f);
}

// ---------------- layer1 (H=1) edge passes ----------------
__global__ void edgeA1_kernel(const int* __restrict__ src, const int* __restrict__ dst, int E) {
    int i = blockIdx.x * blockDim.x + threadIdx.x;
    int EP = E + NN;
    if (i >= EP) return;
    int s, d; bool inv = false;
    if (i < E) { s = src[i]; d = dst[i]; inv = (s == d); }
    else       { s = d = i - E; }
    float e = g_el[s] + g_er[d];
    if (inv) { g_e[i] = -1e30f; return; }
    e = e > 0.f ? e : NEG_SLOPE * e;
    g_e[i] = e;
    atomicMax(&g_m[d], enc_f(e));
}
__global__ void edgeB1_kernel(const int* __restrict__ dst, int E) {
    int i = blockIdx.x * blockDim.x + threadIdx.x;
    int EP = E + NN;
    if (i >= EP) return;
    int d = (i < E) ? dst[i] : i - E;
    float ex = __expf(g_e[i] - dec_f(g_m[d]));
    g_e[i] = ex;
    atomicAdd(&g_s[d], ex);
}
__global__ void edgeC1_kernel(const int* __restrict__ src, const int* __restrict__ dst, int E,
                              float* __restrict__ out) {
    int t = blockIdx.x * blockDim.x + threadIdx.x;
    int w = t >> 5, lane = t & 31;
    if (w >= E + NN) return;
    int s, d;
    if (w < E) { s = src[w]; d = dst[w]; if (s == d) return; }
    else       { s = d = w - E; }
    float alpha = __fdividef(g_e[w], g_s[d]);
#pragma unroll
    for (int j = 0; j < 2; j++) {
        int v = j * 32 + lane;
        if (v < 40) atomicAdd(out + d * 40 + v, g_z1[s * 40 + v] * alpha);
    }
}
__global__ void fin1_kernel(float* __restrict__ out, const float* __restrict__ b1) {
    int i = blockIdx.x * blockDim.x + threadIdx.x;
    if (i >= NN * 40) return;
    float v = out[i] + b1[i % 40];
    out[i] = v > 0.f ? v : (__expf(v) - 1.f);
}

// ---------------- launch ----------------
extern "C" void kernel_launch(void* const* d_in, const int* in_sizes, int n_in,
                              void* d_out, int out_size) {
    const float* x   = (const float*)d_in[0];
    const int*   src = (const int*)d_in[1];
    const int*   dst = (const int*)d_in[2];
    const float* W0  = (const float*)d_in[3];
    const float* al0 = (const float*)d_in[4];
    const float* ar0 = (const float*)d_in[5];
    const float* b0  = (const float*)d_in[6];
    const float* W1  = (const float*)d_in[7];
    const float* al1 = (const float*)d_in[8];
    const float* ar1 = (const float*)d_in[9];
    const float* b1  = (const float*)d_in[10];
    float* out = (float*)d_out;

    const int E  = in_sizes[1];
    const int EP = E + NN;

    // ---- layer 0 ----
    zero0_kernel<<<(NN * 128 + 255) / 256, 256>>>();
    gemm0_kernel<<<(NN + 127) / 128, 256>>>(x, W0, NN);
    attn0_kernel<<<(NN * 4 + 255) / 256, 256>>>(al0, ar0);
    edgeA4_kernel<<<(EP + 255) / 256, 256>>>(src, dst, E);
    edgeB4_kernel<<<(EP + 255) / 256, 256>>>(dst, E);
    edgeC4_kernel<<<(int)(((long)EP * 32 + 255) / 256), 256>>>(src, dst, E);
    fin0_kernel<<<(NN * 128 + 255) / 256, 256>>>(b0);

    // ---- layer 1 ----
    zero1_kernel<<<(NN * 40 + 255) / 256, 256>>>(out);
    gemm1_kernel<<<(NN + 127) / 128, 128>>>(W1, NN);
    attn1_kernel<<<(NN + 255) / 256, 256>>>(al1, ar1);
    edgeA1_kernel<<<(EP + 255) / 256, 256>>>(src, dst, E);
    edgeB1_kernel<<<(EP + 255) / 256, 256>>>(dst, E);
    edgeC1_kernel<<<(int)(((long)EP * 32 + 255) / 256), 256>>>(src, dst, E, out);
    fin1_kernel<<<(NN * 40 + 255) / 256, 256>>>(out, b1);
}

// round 4
// speedup vs baseline: 1.5403x; 1.5403x over previous
#include <cuda_runtime.h>

#define NN 50000
#define EPMAX 850000
#define NEG_SLOPE 0.2f
#define NB_SCAN 98   // ceil(50000/512)

// ---------------- scratch (device globals; no allocation allowed) ----------------
__device__ __align__(16) float g_z0[NN * 128];   // layer0 projected features
__device__ __align__(16) float g_h0[NN * 128];   // layer0 output (elu'd)
__device__ __align__(16) float g_z1[NN * 40];    // layer1 projected features
__device__ __align__(16) float g_el[NN * 4];     // attn left  (layer1 uses [0,NN))
__device__ __align__(16) float g_er[NN * 4];     // attn right
// CSR scratch (built once per call, shared by both layers)
__device__ int g_cnt[NN];        // in-degree (valid edges only)
__device__ int g_rowptr[NN];     // exclusive prefix of cnt
__device__ int g_fill[NN];       // running fill cursor for scatter
__device__ int g_part[128];      // scan partials
__device__ int g_srcs[EPMAX];    // CSR payload: source node per edge

// ---------------- GEMM body: C[nrows,M] = A[nrows,K] @ B[K,M] ----------------
template <int K, int M, int BM, int BK, int TM, int TN>
__device__ __forceinline__ void gemm_body(const float* __restrict__ A,
                                          const float* __restrict__ B,
                                          float* __restrict__ C, int nrows) {
    constexpr int TX = M / TN;
    constexpr int TY = BM / TM;
    constexpr int NT = TX * TY;
    __shared__ float As[BM][BK + 1];
    __shared__ float Bs[BK][M];

    const int tid = threadIdx.x;
    const int tx = tid % TX, ty = tid / TX;
    const int rowBase = blockIdx.x * BM;

    float acc[TM][TN];
#pragma unroll
    for (int i = 0; i < TM; i++)
#pragma unroll
        for (int j = 0; j < TN; j++) acc[i][j] = 0.f;

    for (int k0 = 0; k0 < K; k0 += BK) {
        for (int idx = tid; idx < BM * BK; idx += NT) {
            int r = idx / BK, kk = idx % BK;
            int gr = rowBase + r;
            As[r][kk] = (gr < nrows) ? A[gr * K + k0 + kk] : 0.f;
        }
        for (int idx = tid; idx < BK * M; idx += NT) {
            int kk = idx / M, c = idx % M;
            Bs[kk][c] = B[(k0 + kk) * M + c];
        }
        __syncthreads();
#pragma unroll
        for (int kk = 0; kk < BK; kk++) {
            float a[TM], b[TN];
#pragma unroll
            for (int i = 0; i < TM; i++) a[i] = As[ty * TM + i][kk];
#pragma unroll
            for (int j = 0; j < TN; j++) b[j] = Bs[kk][tx + j * TX];
#pragma unroll
            for (int i = 0; i < TM; i++)
#pragma unroll
                for (int j = 0; j < TN; j++) acc[i][j] = fmaf(a[i], b[j], acc[i][j]);
        }
        __syncthreads();
    }
#pragma unroll
    for (int i = 0; i < TM; i++) {
        int gr = rowBase + ty * TM + i;
        if (gr < nrows) {
#pragma unroll
            for (int j = 0; j < TN; j++) C[gr * M + tx + j * TX] = acc[i][j];
        }
    }
}

__global__ void gemm0_kernel(const float* __restrict__ A, const float* __restrict__ B,
                             int nrows) {
    gemm_body<256, 128, 128, 16, 8, 8>(A, B, g_z0, nrows);
}
__global__ void gemm1_kernel(const float* __restrict__ B, int nrows) {
    gemm_body<128, 40, 128, 16, 8, 5>(g_h0, B, g_z1, nrows);
}

// ---------------- attention scalars ----------------
template <int H, int F>
__device__ __forceinline__ void attn_body(const float* __restrict__ z,
                                          const float* __restrict__ al,
                                          const float* __restrict__ ar) {
    int t = blockIdx.x * blockDim.x + threadIdx.x;
    if (t >= NN * H) return;
    int n = t / H, h = t % H;
    const float* zp = z + n * (H * F) + h * F;
    float sl = 0.f, sr = 0.f;
#pragma unroll
    for (int f = 0; f < F; f++) {
        float v = zp[f];
        sl = fmaf(v, al[h * F + f], sl);
        sr = fmaf(v, ar[h * F + f], sr);
    }
    g_el[t] = sl;
    g_er[t] = sr;
}
__global__ void attn0_kernel(const float* __restrict__ al, const float* __restrict__ ar) {
    attn_body<4, 32>(g_z0, al, ar);
}
__global__ void attn1_kernel(const float* __restrict__ al, const float* __restrict__ ar) {
    attn_body<1, 40>(g_z1, al, ar);
}

// ---------------- CSR build (valid edges: src!=dst originals, plus all self-loops) ----------------
__global__ void csr_zero_kernel() {
    int i = blockIdx.x * blockDim.x + threadIdx.x;
    if (i < NN) g_cnt[i] = 0;
}
__global__ void csr_count_kernel(const int* __restrict__ src, const int* __restrict__ dst, int E) {
    int i = blockIdx.x * blockDim.x + threadIdx.x;
    int EP = E + NN;
    if (i >= EP) return;
    int d;
    if (i < E) {
        int s = src[i];
        d = dst[i];
        if (s == d) return;   // invalid edge: excluded entirely
    } else {
        d = i - E;            // appended self-loop
    }
    atomicAdd(&g_cnt[d], 1);
}
__global__ void scan1_kernel() {
    __shared__ int sh[512];
    int i = blockIdx.x * 512 + threadIdx.x;
    sh[threadIdx.x] = (i < NN) ? g_cnt[i] : 0;
    __syncthreads();
    for (int o = 256; o > 0; o >>= 1) {
        if (threadIdx.x < o) sh[threadIdx.x] += sh[threadIdx.x + o];
        __syncthreads();
    }
    if (threadIdx.x == 0) g_part[blockIdx.x] = sh[0];
}
__global__ void scan2_kernel(int nb) {
    if (threadIdx.x == 0) {
        int acc = 0;
        for (int b = 0; b < nb; b++) { int v = g_part[b]; g_part[b] = acc; acc += v; }
    }
}
__global__ void scan3_kernel() {
    __shared__ int sh[512];
    int i = blockIdx.x * 512 + threadIdx.x;
    int v = (i < NN) ? g_cnt[i] : 0;
    sh[threadIdx.x] = v;
    __syncthreads();
    for (int o = 1; o < 512; o <<= 1) {
        int t = (threadIdx.x >= o) ? sh[threadIdx.x - o] : 0;
        __syncthreads();
        sh[threadIdx.x] += t;
        __syncthreads();
    }
    if (i < NN) {
        int excl = sh[threadIdx.x] - v + g_part[blockIdx.x];
        g_rowptr[i] = excl;
        g_fill[i] = excl;
    }
}
__global__ void csr_scatter_kernel(const int* __restrict__ src, const int* __restrict__ dst, int E) {
    int i = blockIdx.x * blockDim.x + threadIdx.x;
    int EP = E + NN;
    if (i >= EP) return;
    int s, d;
    if (i < E) {
        s = src[i]; d = dst[i];
        if (s == d) return;
    } else {
        s = d = i - E;
    }
    int pos = atomicAdd(&g_fill[d], 1);
    g_srcs[pos] = s;
}

// ---------------- layer0 gather: warp per node, H=4, F=32, fused bias+ELU ----------------
__global__ void gather0_kernel(const float* __restrict__ b0) {
    int w = (blockIdx.x * blockDim.x + threadIdx.x) >> 5;
    int lane = threadIdx.x & 31;
    if (w >= NN) return;
    const int beg = g_rowptr[w];
    const int deg = g_cnt[w];      // >= 1 (self-loop)
    const float4 erd = *(const float4*)(g_er + w * 4);

    // phase 1: per-head max over in-edges
    float m0 = -1e30f, m1 = -1e30f, m2 = -1e30f, m3 = -1e30f;
    for (int t = lane; t < deg; t += 32) {
        int s = g_srcs[beg + t];
        float4 el = *(const float4*)(g_el + s * 4);
        float e0 = el.x + erd.x; e0 = e0 > 0.f ? e0 : NEG_SLOPE * e0; m0 = fmaxf(m0, e0);
        float e1 = el.y + erd.y; e1 = e1 > 0.f ? e1 : NEG_SLOPE * e1; m1 = fmaxf(m1, e1);
        float e2 = el.z + erd.z; e2 = e2 > 0.f ? e2 : NEG_SLOPE * e2; m2 = fmaxf(m2, e2);
        float e3 = el.w + erd.w; e3 = e3 > 0.f ? e3 : NEG_SLOPE * e3; m3 = fmaxf(m3, e3);
    }
#pragma unroll
    for (int o = 16; o > 0; o >>= 1) {
        m0 = fmaxf(m0, __shfl_xor_sync(0xffffffffu, m0, o));
        m1 = fmaxf(m1, __shfl_xor_sync(0xffffffffu, m1, o));
        m2 = fmaxf(m2, __shfl_xor_sync(0xffffffffu, m2, o));
        m3 = fmaxf(m3, __shfl_xor_sync(0xffffffffu, m3, o));
    }

    // phase 2: per-head exp-sum
    float s0 = 0.f, s1 = 0.f, s2 = 0.f, s3 = 0.f;
    for (int t = lane; t < deg; t += 32) {
        int s = g_srcs[beg + t];
        float4 el = *(const float4*)(g_el + s * 4);
        float e0 = el.x + erd.x; e0 = e0 > 0.f ? e0 : NEG_SLOPE * e0;
        float e1 = el.y + erd.y; e1 = e1 > 0.f ? e1 : NEG_SLOPE * e1;
        float e2 = el.z + erd.z; e2 = e2 > 0.f ? e2 : NEG_SLOPE * e2;
        float e3 = el.w + erd.w; e3 = e3 > 0.f ? e3 : NEG_SLOPE * e3;
        s0 += __expf(e0 - m0); s1 += __expf(e1 - m1);
        s2 += __expf(e2 - m2); s3 += __expf(e3 - m3);
    }
#pragma unroll
    for (int o = 16; o > 0; o >>= 1) {
        s0 += __shfl_xor_sync(0xffffffffu, s0, o);
        s1 += __shfl_xor_sync(0xffffffffu, s1, o);
        s2 += __shfl_xor_sync(0xffffffffu, s2, o);
        s3 += __shfl_xor_sync(0xffffffffu, s3, o);
    }
    const float i0 = __frcp_rn(s0), i1 = __frcp_rn(s1), i2 = __frcp_rn(s2), i3 = __frcp_rn(s3);

    // phase 3: weighted feature accumulation (lane owns feature f = h*32+lane per head)
    float a0 = 0.f, a1 = 0.f, a2 = 0.f, a3 = 0.f;
    for (int t = 0; t < deg; t++) {
        int s = g_srcs[beg + t];                     // uniform broadcast load
        float4 el = *(const float4*)(g_el + s * 4);  // uniform broadcast load
        float e0 = el.x + erd.x; e0 = e0 > 0.f ? e0 : NEG_SLOPE * e0;
        float e1 = el.y + erd.y; e1 = e1 > 0.f ? e1 : NEG_SLOPE * e1;
        float e2 = el.z + erd.z; e2 = e2 > 0.f ? e2 : NEG_SLOPE * e2;
        float e3 = el.w + erd.w; e3 = e3 > 0.f ? e3 : NEG_SLOPE * e3;
        float al0 = __expf(e0 - m0) * i0;
        float al1 = __expf(e1 - m1) * i1;
        float al2 = __expf(e2 - m2) * i2;
        float al3 = __expf(e3 - m3) * i3;
        const float* zr = g_z0 + s * 128;
        a0 = fmaf(al0, zr[lane],      a0);
        a1 = fmaf(al1, zr[32 + lane], a1);
        a2 = fmaf(al2, zr[64 + lane], a2);
        a3 = fmaf(al3, zr[96 + lane], a3);
    }
    // fused bias + ELU, write h0
    float* hr = g_h0 + w * 128;
    float v;
    v = a0 + b0[lane];       hr[lane]      = v > 0.f ? v : (__expf(v) - 1.f);
    v = a1 + b0[32 + lane];  hr[32 + lane] = v > 0.f ? v : (__expf(v) - 1.f);
    v = a2 + b0[64 + lane];  hr[64 + lane] = v > 0.f ? v : (__expf(v) - 1.f);
    v = a3 + b0[96 + lane];  hr[96 + lane] = v > 0.f ? v : (__expf(v) - 1.f);
}

// ---------------- layer1 gather: warp per node, H=1, C=40, fused bias+ELU ----------------
__global__ void gather1_kernel(float* __restrict__ out, const float* __restrict__ b1) {
    int w = (blockIdx.x * blockDim.x + threadIdx.x) >> 5;
    int lane = threadIdx.x & 31;
    if (w >= NN) return;
    const int beg = g_rowptr[w];
    const int deg = g_cnt[w];
    const float erd = g_er[w];

    float m = -1e30f;
    for (int t = lane; t < deg; t += 32) {
        int s = g_srcs[beg + t];
        float e = g_el[s] + erd; e = e > 0.f ? e : NEG_SLOPE * e;
        m = fmaxf(m, e);
    }
#pragma unroll
    for (int o = 16; o > 0; o >>= 1) m = fmaxf(m, __shfl_xor_sync(0xffffffffu, m, o));

    float ssum = 0.f;
    for (int t = lane; t < deg; t += 32) {
        int s = g_srcs[beg + t];
        float e = g_el[s] + erd; e = e > 0.f ? e : NEG_SLOPE * e;
        ssum += __expf(e - m);
    }
#pragma unroll
    for (int o = 16; o > 0; o >>= 1) ssum += __shfl_xor_sync(0xffffffffu, ssum, o);
    const float inv = __frcp_rn(ssum);

    float a0 = 0.f, a1 = 0.f;
    for (int t = 0; t < deg; t++) {
        int s = g_srcs[beg + t];
        float e = g_el[s] + erd; e = e > 0.f ? e : NEG_SLOPE * e;
        float al = __expf(e - m) * inv;
        const float* zr = g_z1 + s * 40;
        a0 = fmaf(al, zr[lane], a0);
        if (lane < 8) a1 = fmaf(al, zr[32 + lane], a1);
    }
    float v = a0 + b1[lane];
    out[w * 40 + lane] = v > 0.f ? v : (__expf(v) - 1.f);
    if (lane < 8) {
        v = a1 + b1[32 + lane];
        out[w * 40 + 32 + lane] = v > 0.f ? v : (__expf(v) - 1.f);
    }
}

// ---------------- launch ----------------
extern "C" void kernel_launch(void* const* d_in, const int* in_sizes, int n_in,
                              void* d_out, int out_size) {
    const float* x   = (const float*)d_in[0];
    const int*   src = (const int*)d_in[1];
    const int*   dst = (const int*)d_in[2];
    const float* W0  = (const float*)d_in[3];
    const float* al0 = (const float*)d_in[4];
    const float* ar0 = (const float*)d_in[5];
    const float* b0  = (const float*)d_in[6];
    const float* W1  = (const float*)d_in[7];
    const float* al1 = (const float*)d_in[8];
    const float* ar1 = (const float*)d_in[9];
    const float* b1  = (const float*)d_in[10];
    float* out = (float*)d_out;

    const int E  = in_sizes[1];
    const int EP = E + NN;

    // ---- CSR build (shared by both layers) ----
    csr_zero_kernel<<<(NN + 255) / 256, 256>>>();
    csr_count_kernel<<<(EP + 255) / 256, 256>>>(src, dst, E);
    scan1_kernel<<<NB_SCAN, 512>>>();
    scan2_kernel<<<1, 32>>>(NB_SCAN);
    scan3_kernel<<<NB_SCAN, 512>>>();
    csr_scatter_kernel<<<(EP + 255) / 256, 256>>>(src, dst, E);

    // ---- layer 0 ----
    gemm0_kernel<<<(NN + 127) / 128, 256>>>(x, W0, NN);
    attn0_kernel<<<(NN * 4 + 255) / 256, 256>>>(al0, ar0);
    gather0_kernel<<<(NN * 32 + 255) / 256, 256>>>(b0);

    // ---- layer 1 ----
    gemm1_kernel<<<(NN + 127) / 128, 128>>>(W1, NN);
    attn1_kernel<<<(NN + 255) / 256, 256>>>(al1, ar1);
    gather1_kernel<<<(NN * 32 + 255) / 256, 256>>>(out, b1);
}

// round 5
// speedup vs baseline: 1.7663x; 1.1468x over previous
#include <cuda_runtime.h>
#include <cuda_bf16.h>
#include <cstdint>

#define NN 50000
#define EPMAX 850000
#define NEG_SLOPE 0.2f
#define NB_SCAN 98   // ceil(50000/512)

// ---------------- scratch (device globals; no allocation allowed) ----------------
__device__ __align__(16) float g_z0[NN * 128];   // layer0 projected features
__device__ __align__(16) float g_h0[NN * 128];   // layer0 output (elu'd)
__device__ __align__(16) float g_z1[NN * 40];    // layer1 projected features
__device__ __align__(16) float g_el[NN * 4];     // attn left  (layer1 uses [0,NN))
__device__ __align__(16) float g_er[NN * 4];     // attn right
// CSR scratch (built once per call, shared by both layers)
__device__ int g_cnt[NN];
__device__ int g_rowptr[NN];
__device__ int g_fill[NN];
__device__ int g_part[128];
__device__ int g_srcs[EPMAX];

// ================= split-bf16 tensor-core GEMM: g_z0 = x @ W0 =================
// C[nrows,128] = A[nrows,256] * B[256,128], fp32 in/out.
// Each fp32 value v is split v = hi + lo (both bf16); product approximated by
// hi*hi + hi*lo + lo*hi (drop lo*lo): ~17 effective mantissa bits.
#define G0_K 256
#define G0_M 128
#define G0_BK 32
#define G0_PAD 40   // smem row stride in bf16 (20 words -> conflict-free frags)

__device__ __forceinline__ void mma_bf16(float& c0, float& c1, float& c2, float& c3,
                                         uint32_t a0, uint32_t a1, uint32_t a2, uint32_t a3,
                                         uint32_t b0, uint32_t b1) {
    asm volatile(
        "mma.sync.aligned.m16n8k16.row.col.f32.bf16.bf16.f32 "
        "{%0,%1,%2,%3}, {%4,%5,%6,%7}, {%8,%9}, {%0,%1,%2,%3};"
        : "+f"(c0), "+f"(c1), "+f"(c2), "+f"(c3)
        : "r"(a0), "r"(a1), "r"(a2), "r"(a3), "r"(b0), "r"(b1));
}

__global__ void __launch_bounds__(256) gemm0_mma_kernel(const float* __restrict__ A,
                                                        const float* __restrict__ B,
                                                        int nrows) {
    __shared__ __nv_bfloat16 Ah[128][G0_PAD];
    __shared__ __nv_bfloat16 Al[128][G0_PAD];
    __shared__ __nv_bfloat16 Bh[128][G0_PAD];   // transposed: [n][k]
    __shared__ __nv_bfloat16 Bl[128][G0_PAD];

    const int tid = threadIdx.x;
    const int lane = tid & 31;
    const int wid = tid >> 5;
    const int warp_m = wid & 3;         // 4 warps over 128 rows (32 each)
    const int warp_n = wid >> 2;        // 2 warps over 128 cols (64 each)
    const int rowBase = blockIdx.x * 128;
    const int g = lane >> 2;            // fragment row group
    const int q = lane & 3;             // fragment col quad

    float acc[2][8][4];
#pragma unroll
    for (int mt = 0; mt < 2; mt++)
#pragma unroll
        for (int nt = 0; nt < 8; nt++)
#pragma unroll
            for (int i = 0; i < 4; i++) acc[mt][nt][i] = 0.f;

    for (int kt = 0; kt < G0_K / G0_BK; kt++) {
        // ---- load A tile 128x32 (coalesced float4), split to bf16 hi/lo ----
#pragma unroll
        for (int i = 0; i < 4; i++) {
            int idx = tid + i * 256;            // 0..1023
            int row = idx >> 3;
            int kq  = idx & 7;
            float4 v = make_float4(0.f, 0.f, 0.f, 0.f);
            if (rowBase + row < nrows)
                v = *(const float4*)(A + (size_t)(rowBase + row) * G0_K + kt * G0_BK + kq * 4);
            int kl = kq * 4;
            const float vv[4] = {v.x, v.y, v.z, v.w};
#pragma unroll
            for (int j = 0; j < 4; j++) {
                __nv_bfloat16 h = __float2bfloat16_rn(vv[j]);
                Ah[row][kl + j] = h;
                Al[row][kl + j] = __float2bfloat16_rn(vv[j] - __bfloat162float(h));
            }
        }
        // ---- load B tile 32x128, store transposed [n][k], split hi/lo ----
#pragma unroll
        for (int i = 0; i < 4; i++) {
            int idx = tid + i * 256;            // 0..1023
            int kr = idx >> 5;                  // 0..31
            int nq = idx & 31;
            float4 v = *(const float4*)(B + (size_t)(kt * G0_BK + kr) * G0_M + nq * 4);
            const float vv[4] = {v.x, v.y, v.z, v.w};
#pragma unroll
            for (int j = 0; j < 4; j++) {
                __nv_bfloat16 h = __float2bfloat16_rn(vv[j]);
                Bh[nq * 4 + j][kr] = h;
                Bl[nq * 4 + j][kr] = __float2bfloat16_rn(vv[j] - __bfloat162float(h));
            }
        }
        __syncthreads();

#pragma unroll
        for (int ks = 0; ks < 2; ks++) {        // two k16 steps per BK=32
            const int w0 = ks * 8 + q;          // word index within padded row
            uint32_t aH[2][4], aL[2][4];
#pragma unroll
            for (int mt = 0; mt < 2; mt++) {
                int r0 = warp_m * 32 + mt * 16 + g;
                const uint32_t* ph0 = (const uint32_t*)&Ah[r0][0];
                const uint32_t* ph8 = (const uint32_t*)&Ah[r0 + 8][0];
                const uint32_t* pl0 = (const uint32_t*)&Al[r0][0];
                const uint32_t* pl8 = (const uint32_t*)&Al[r0 + 8][0];
                aH[mt][0] = ph0[w0]; aH[mt][1] = ph8[w0];
                aH[mt][2] = ph0[w0 + 4]; aH[mt][3] = ph8[w0 + 4];
                aL[mt][0] = pl0[w0]; aL[mt][1] = pl8[w0];
                aL[mt][2] = pl0[w0 + 4]; aL[mt][3] = pl8[w0 + 4];
            }
#pragma unroll
            for (int nt = 0; nt < 8; nt++) {
                int n0 = warp_n * 64 + nt * 8 + g;
                const uint32_t* pbh = (const uint32_t*)&Bh[n0][0];
                const uint32_t* pbl = (const uint32_t*)&Bl[n0][0];
                uint32_t bH0 = pbh[w0], bH1 = pbh[w0 + 4];
                uint32_t bL0 = pbl[w0], bL1 = pbl[w0 + 4];
#pragma unroll
                for (int mt = 0; mt < 2; mt++) {
                    float* c = acc[mt][nt];
                    mma_bf16(c[0], c[1], c[2], c[3],
                             aH[mt][0], aH[mt][1], aH[mt][2], aH[mt][3], bH0, bH1);
                    mma_bf16(c[0], c[1], c[2], c[3],
                             aH[mt][0], aH[mt][1], aH[mt][2], aH[mt][3], bL0, bL1);
                    mma_bf16(c[0], c[1], c[2], c[3],
                             aL[mt][0], aL[mt][1], aL[mt][2], aL[mt][3], bH0, bH1);
                }
            }
        }
        __syncthreads();
    }

    // ---- epilogue: write C rows ----
#pragma unroll
    for (int mt = 0; mt < 2; mt++) {
        int r0 = rowBase + warp_m * 32 + mt * 16 + g;
        int c0 = warp_n * 64 + q * 2;
#pragma unroll
        for (int nt = 0; nt < 8; nt++) {
            float* c = acc[mt][nt];
            if (r0 < nrows)
                *(float2*)(g_z0 + (size_t)r0 * 128 + c0 + nt * 8) = make_float2(c[0], c[1]);
            if (r0 + 8 < nrows)
                *(float2*)(g_z0 + (size_t)(r0 + 8) * 128 + c0 + nt * 8) = make_float2(c[2], c[3]);
        }
    }
}

// ---------------- SIMT GEMM (layer 1): C[nrows,M] = A[nrows,K] @ B[K,M] ----------------
template <int K, int M, int BM, int BK, int TM, int TN>
__device__ __forceinline__ void gemm_body(const float* __restrict__ A,
                                          const float* __restrict__ B,
                                          float* __restrict__ C, int nrows) {
    constexpr int TX = M / TN;
    constexpr int TY = BM / TM;
    constexpr int NT = TX * TY;
    __shared__ float As[BM][BK + 1];
    __shared__ float Bs[BK][M];

    const int tid = threadIdx.x;
    const int tx = tid % TX, ty = tid / TX;
    const int rowBase = blockIdx.x * BM;

    float acc[TM][TN];
#pragma unroll
    for (int i = 0; i < TM; i++)
#pragma unroll
        for (int j = 0; j < TN; j++) acc[i][j] = 0.f;

    for (int k0 = 0; k0 < K; k0 += BK) {
        for (int idx = tid; idx < BM * BK; idx += NT) {
            int r = idx / BK, kk = idx % BK;
            int gr = rowBase + r;
            As[r][kk] = (gr < nrows) ? A[gr * K + k0 + kk] : 0.f;
        }
        for (int idx = tid; idx < BK * M; idx += NT) {
            int kk = idx / M, c = idx % M;
            Bs[kk][c] = B[(k0 + kk) * M + c];
        }
        __syncthreads();
#pragma unroll
        for (int kk = 0; kk < BK; kk++) {
            float a[TM], b[TN];
#pragma unroll
            for (int i = 0; i < TM; i++) a[i] = As[ty * TM + i][kk];
#pragma unroll
            for (int j = 0; j < TN; j++) b[j] = Bs[kk][tx + j * TX];
#pragma unroll
            for (int i = 0; i < TM; i++)
#pragma unroll
                for (int j = 0; j < TN; j++) acc[i][j] = fmaf(a[i], b[j], acc[i][j]);
        }
        __syncthreads();
    }
#pragma unroll
    for (int i = 0; i < TM; i++) {
        int gr = rowBase + ty * TM + i;
        if (gr < nrows) {
#pragma unroll
            for (int j = 0; j < TN; j++) C[gr * M + tx + j * TX] = acc[i][j];
        }
    }
}
__global__ void gemm1_kernel(const float* __restrict__ B, int nrows) {
    gemm_body<128, 40, 128, 16, 8, 5>(g_h0, B, g_z1, nrows);
}

// ---------------- attention scalars ----------------
template <int H, int F>
__device__ __forceinline__ void attn_body(const float* __restrict__ z,
                                          const float* __restrict__ al,
                                          const float* __restrict__ ar) {
    int t = blockIdx.x * blockDim.x + threadIdx.x;
    if (t >= NN * H) return;
    int n = t / H, h = t % H;
    const float* zp = z + n * (H * F) + h * F;
    float sl = 0.f, sr = 0.f;
#pragma unroll
    for (int f = 0; f < F; f++) {
        float v = zp[f];
        sl = fmaf(v, al[h * F + f], sl);
        sr = fmaf(v, ar[h * F + f], sr);
    }
    g_el[t] = sl;
    g_er[t] = sr;
}
__global__ void attn0_kernel(const float* __restrict__ al, const float* __restrict__ ar) {
    attn_body<4, 32>(g_z0, al, ar);
}
__global__ void attn1_kernel(const float* __restrict__ al, const float* __restrict__ ar) {
    attn_body<1, 40>(g_z1, al, ar);
}

// ---------------- CSR build ----------------
__global__ void csr_zero_kernel() {
    int i = blockIdx.x * blockDim.x + threadIdx.x;
    if (i < NN) g_cnt[i] = 0;
}
__global__ void csr_count_kernel(const int* __restrict__ src, const int* __restrict__ dst, int E) {
    int i = blockIdx.x * blockDim.x + threadIdx.x;
    int EP = E + NN;
    if (i >= EP) return;
    int d;
    if (i < E) {
        int s = src[i];
        d = dst[i];
        if (s == d) return;
    } else {
        d = i - E;
    }
    atomicAdd(&g_cnt[d], 1);
}
__global__ void scan1_kernel() {
    __shared__ int sh[512];
    int i = blockIdx.x * 512 + threadIdx.x;
    sh[threadIdx.x] = (i < NN) ? g_cnt[i] : 0;
    __syncthreads();
    for (int o = 256; o > 0; o >>= 1) {
        if (threadIdx.x < o) sh[threadIdx.x] += sh[threadIdx.x + o];
        __syncthreads();
    }
    if (threadIdx.x == 0) g_part[blockIdx.x] = sh[0];
}
// parallel exclusive scan of g_part[0..nb), nb <= 128, one block of 128 threads
__global__ void scan2_kernel(int nb) {
    int t = threadIdx.x;
    int lane = t & 31, w = t >> 5;
    int v = (t < nb) ? g_part[t] : 0;
    int x = v;
#pragma unroll
    for (int o = 1; o < 32; o <<= 1) {
        int y = __shfl_up_sync(0xffffffffu, x, o);
        if (lane >= o) x += y;
    }
    __shared__ int ws[4];
    if (lane == 31) ws[w] = x;
    __syncthreads();
    int add = 0;
#pragma unroll
    for (int i = 0; i < 4; i++) add += (i < w) ? ws[i] : 0;
    if (t < nb) g_part[t] = x + add - v;   // exclusive
}
__global__ void scan3_kernel() {
    __shared__ int sh[512];
    int i = blockIdx.x * 512 + threadIdx.x;
    int v = (i < NN) ? g_cnt[i] : 0;
    sh[threadIdx.x] = v;
    __syncthreads();
    for (int o = 1; o < 512; o <<= 1) {
        int t = (threadIdx.x >= o) ? sh[threadIdx.x - o] : 0;
        __syncthreads();
        sh[threadIdx.x] += t;
        __syncthreads();
    }
    if (i < NN) {
        int excl = sh[threadIdx.x] - v + g_part[blockIdx.x];
        g_rowptr[i] = excl;
        g_fill[i] = excl;
    }
}
__global__ void csr_scatter_kernel(const int* __restrict__ src, const int* __restrict__ dst, int E) {
    int i = blockIdx.x * blockDim.x + threadIdx.x;
    int EP = E + NN;
    if (i >= EP) return;
    int s, d;
    if (i < E) {
        s = src[i]; d = dst[i];
        if (s == d) return;
    } else {
        s = d = i - E;
    }
    int pos = atomicAdd(&g_fill[d], 1);
    g_srcs[pos] = s;
}

// ---------------- layer0 gather: warp per node, H=4, F=32, fused bias+ELU ----------------
__global__ void gather0_kernel(const float* __restrict__ b0) {
    int w = (blockIdx.x * blockDim.x + threadIdx.x) >> 5;
    int lane = threadIdx.x & 31;
    if (w >= NN) return;
    const int beg = g_rowptr[w];
    const int deg = g_cnt[w];
    const float4 erd = *(const float4*)(g_er + w * 4);

    float m0 = -1e30f, m1 = -1e30f, m2 = -1e30f, m3 = -1e30f;
    for (int t = lane; t < deg; t += 32) {
        int s = g_srcs[beg + t];
        float4 el = *(const float4*)(g_el + s * 4);
        float e0 = el.x + erd.x; e0 = e0 > 0.f ? e0 : NEG_SLOPE * e0; m0 = fmaxf(m0, e0);
        float e1 = el.y + erd.y; e1 = e1 > 0.f ? e1 : NEG_SLOPE * e1; m1 = fmaxf(m1, e1);
        float e2 = el.z + erd.z; e2 = e2 > 0.f ? e2 : NEG_SLOPE * e2; m2 = fmaxf(m2, e2);
        float e3 = el.w + erd.w; e3 = e3 > 0.f ? e3 : NEG_SLOPE * e3; m3 = fmaxf(m3, e3);
    }
#pragma unroll
    for (int o = 16; o > 0; o >>= 1) {
        m0 = fmaxf(m0, __shfl_xor_sync(0xffffffffu, m0, o));
        m1 = fmaxf(m1, __shfl_xor_sync(0xffffffffu, m1, o));
        m2 = fmaxf(m2, __shfl_xor_sync(0xffffffffu, m2, o));
        m3 = fmaxf(m3, __shfl_xor_sync(0xffffffffu, m3, o));
    }

    float s0 = 0.f, s1 = 0.f, s2 = 0.f, s3 = 0.f;
    for (int t = lane; t < deg; t += 32) {
        int s = g_srcs[beg + t];
        float4 el = *(const float4*)(g_el + s * 4);
        float e0 = el.x + erd.x; e0 = e0 > 0.f ? e0 : NEG_SLOPE * e0;
        float e1 = el.y + erd.y; e1 = e1 > 0.f ? e1 : NEG_SLOPE * e1;
        float e2 = el.z + erd.z; e2 = e2 > 0.f ? e2 : NEG_SLOPE * e2;
        float e3 = el.w + erd.w; e3 = e3 > 0.f ? e3 : NEG_SLOPE * e3;
        s0 += __expf(e0 - m0); s1 += __expf(e1 - m1);
        s2 += __expf(e2 - m2); s3 += __expf(e3 - m3);
    }
#pragma unroll
    for (int o = 16; o > 0; o >>= 1) {
        s0 += __shfl_xor_sync(0xffffffffu, s0, o);
        s1 += __shfl_xor_sync(0xffffffffu, s1, o);
        s2 += __shfl_xor_sync(0xffffffffu, s2, o);
        s3 += __shfl_xor_sync(0xffffffffu, s3, o);
    }
    const float i0 = __frcp_rn(s0), i1 = __frcp_rn(s1), i2 = __frcp_rn(s2), i3 = __frcp_rn(s3);

    float a0 = 0.f, a1 = 0.f, a2 = 0.f, a3 = 0.f;
    for (int t = 0; t < deg; t++) {
        int s = g_srcs[beg + t];
        float4 el = *(const float4*)(g_el + s * 4);
        float e0 = el.x + erd.x; e0 = e0 > 0.f ? e0 : NEG_SLOPE * e0;
        float e1 = el.y + erd.y; e1 = e1 > 0.f ? e1 : NEG_SLOPE * e1;
        float e2 = el.z + erd.z; e2 = e2 > 0.f ? e2 : NEG_SLOPE * e2;
        float e3 = el.w + erd.w; e3 = e3 > 0.f ? e3 : NEG_SLOPE * e3;
        float al0 = __expf(e0 - m0) * i0;
        float al1 = __expf(e1 - m1) * i1;
        float al2 = __expf(e2 - m2) * i2;
        float al3 = __expf(e3 - m3) * i3;
        const float* zr = g_z0 + s * 128;
        a0 = fmaf(al0, zr[lane],      a0);
        a1 = fmaf(al1, zr[32 + lane], a1);
        a2 = fmaf(al2, zr[64 + lane], a2);
        a3 = fmaf(al3, zr[96 + lane], a3);
    }
    float* hr = g_h0 + w * 128;
    float v;
    v = a0 + b0[lane];       hr[lane]      = v > 0.f ? v : (__expf(v) - 1.f);
    v = a1 + b0[32 + lane];  hr[32 + lane] = v > 0.f ? v : (__expf(v) - 1.f);
    v = a2 + b0[64 + lane];  hr[64 + lane] = v > 0.f ? v : (__expf(v) - 1.f);
    v = a3 + b0[96 + lane];  hr[96 + lane] = v > 0.f ? v : (__expf(v) - 1.f);
}

// ---------------- layer1 gather ----------------
__global__ void gather1_kernel(float* __restrict__ out, const float* __restrict__ b1) {
    int w = (blockIdx.x * blockDim.x + threadIdx.x) >> 5;
    int lane = threadIdx.x & 31;
    if (w >= NN) return;
    const int beg = g_rowptr[w];
    const int deg = g_cnt[w];
    const float erd = g_er[w];

    float m = -1e30f;
    for (int t = lane; t < deg; t += 32) {
        int s = g_srcs[beg + t];
        float e = g_el[s] + erd; e = e > 0.f ? e : NEG_SLOPE * e;
        m = fmaxf(m, e);
    }
#pragma unroll
    for (int o = 16; o > 0; o >>= 1) m = fmaxf(m, __shfl_xor_sync(0xffffffffu, m, o));

    float ssum = 0.f;
    for (int t = lane; t < deg; t += 32) {
        int s = g_srcs[beg + t];
        float e = g_el[s] + erd; e = e > 0.f ? e : NEG_SLOPE * e;
        ssum += __expf(e - m);
    }
#pragma unroll
    for (int o = 16; o > 0; o >>= 1) ssum += __shfl_xor_sync(0xffffffffu, ssum, o);
    const float inv = __frcp_rn(ssum);

    float a0 = 0.f, a1 = 0.f;
    for (int t = 0; t < deg; t++) {
        int s = g_srcs[beg + t];
        float e = g_el[s] + erd; e = e > 0.f ? e : NEG_SLOPE * e;
        float al = __expf(e - m) * inv;
        const float* zr = g_z1 + s * 40;
        a0 = fmaf(al, zr[lane], a0);
        if (lane < 8) a1 = fmaf(al, zr[32 + lane], a1);
    }
    float v = a0 + b1[lane];
    out[w * 40 + lane] = v > 0.f ? v : (__expf(v) - 1.f);
    if (lane < 8) {
        v = a1 + b1[32 + lane];
        out[w * 40 + 32 + lane] = v > 0.f ? v : (__expf(v) - 1.f);
    }
}

// ---------------- launch ----------------
extern "C" void kernel_launch(void* const* d_in, const int* in_sizes, int n_in,
                              void* d_out, int out_size) {
    const float* x   = (const float*)d_in[0];
    const int*   src = (const int*)d_in[1];
    const int*   dst = (const int*)d_in[2];
    const float* W0  = (const float*)d_in[3];
    const float* al0 = (const float*)d_in[4];
    const float* ar0 = (const float*)d_in[5];
    const float* b0  = (const float*)d_in[6];
    const float* W1  = (const float*)d_in[7];
    const float* al1 = (const float*)d_in[8];
    const float* ar1 = (const float*)d_in[9];
    const float* b1  = (const float*)d_in[10];
    float* out = (float*)d_out;

    const int E  = in_sizes[1];
    const int EP = E + NN;

    // ---- CSR build (shared by both layers) ----
    csr_zero_kernel<<<(NN + 255) / 256, 256>>>();
    csr_count_kernel<<<(EP + 255) / 256, 256>>>(src, dst, E);
    scan1_kernel<<<NB_SCAN, 512>>>();
    scan2_kernel<<<1, 128>>>(NB_SCAN);
    scan3_kernel<<<NB_SCAN, 512>>>();
    csr_scatter_kernel<<<(EP + 255) / 256, 256>>>(src, dst, E);

    // ---- layer 0 ----
    gemm0_mma_kernel<<<(NN + 127) / 128, 256>>>(x, W0, NN);
    attn0_kernel<<<(NN * 4 + 255) / 256, 256>>>(al0, ar0);
    gather0_kernel<<<(NN * 32 + 255) / 256, 256>>>(b0);

    // ---- layer 1 ----
    gemm1_kernel<<<(NN + 127) / 128, 128>>>(W1, NN);
    attn1_kernel<<<(NN + 255) / 256, 256>>>(al1, ar1);
    gather1_kernel<<<(NN * 32 + 255) / 256, 256>>>(out, b1);
}

// round 6
// speedup vs baseline: 2.1327x; 1.2074x over previous
#include <cuda_runtime.h>
#include <cuda_bf16.h>
#include <cstdint>

#define NN 50000
#define EPMAX 850000
#define NEG_SLOPE 0.2f
#define NB_SCAN 98   // ceil(50000/512)

// ---------------- scratch (device globals; no allocation allowed) ----------------
__device__ __align__(16) float g_z0[NN * 128];   // layer0 projected features
__device__ __align__(16) float g_h0[NN * 128];   // layer0 output (elu'd)
__device__ __align__(16) float g_z1[NN * 40];    // layer1 projected features
__device__ __align__(16) float g_el[NN * 4];     // attn left  (layer1 uses [0,NN))
__device__ __align__(16) float g_er[NN * 4];     // attn right
// CSR scratch
__device__ int g_cnt[NN];
__device__ int g_rowptr[NN];
__device__ int g_fill[NN];
__device__ int g_part[128];
__device__ int g_srcs[EPMAX];

// ================= split-bf16 MMA helper =================
__device__ __forceinline__ void mma_bf16(float& c0, float& c1, float& c2, float& c3,
                                         uint32_t a0, uint32_t a1, uint32_t a2, uint32_t a3,
                                         uint32_t b0, uint32_t b1) {
    asm volatile(
        "mma.sync.aligned.m16n8k16.row.col.f32.bf16.bf16.f32 "
        "{%0,%1,%2,%3}, {%4,%5,%6,%7}, {%8,%9}, {%0,%1,%2,%3};"
        : "+f"(c0), "+f"(c1), "+f"(c2), "+f"(c3)
        : "r"(a0), "r"(a1), "r"(a2), "r"(a3), "r"(b0), "r"(b1));
}

// ================= gemm0: g_z0 = x @ W0  (+fused attn0 el/er) =================
#define G0_K 256
#define G0_M 128
#define G0_BK 32
#define G0_PAD 40

__global__ void __launch_bounds__(256) gemm0_mma_kernel(const float* __restrict__ A,
                                                        const float* __restrict__ B,
                                                        const float* __restrict__ al0,
                                                        const float* __restrict__ ar0,
                                                        int nrows) {
    __shared__ __nv_bfloat16 Ah[128][G0_PAD];
    __shared__ __nv_bfloat16 Al[128][G0_PAD];
    __shared__ __nv_bfloat16 Bh[128][G0_PAD];   // transposed: [n][k]
    __shared__ __nv_bfloat16 Bl[128][G0_PAD];

    const int tid = threadIdx.x;
    const int lane = tid & 31;
    const int wid = tid >> 5;
    const int warp_m = wid & 3;
    const int warp_n = wid >> 2;
    const int rowBase = blockIdx.x * 128;
    const int g = lane >> 2;
    const int q = lane & 3;

    float acc[2][8][4];
#pragma unroll
    for (int mt = 0; mt < 2; mt++)
#pragma unroll
        for (int nt = 0; nt < 8; nt++)
#pragma unroll
            for (int i = 0; i < 4; i++) acc[mt][nt][i] = 0.f;

    for (int kt = 0; kt < G0_K / G0_BK; kt++) {
#pragma unroll
        for (int i = 0; i < 4; i++) {
            int idx = tid + i * 256;
            int row = idx >> 3;
            int kq  = idx & 7;
            float4 v = make_float4(0.f, 0.f, 0.f, 0.f);
            if (rowBase + row < nrows)
                v = *(const float4*)(A + (size_t)(rowBase + row) * G0_K + kt * G0_BK + kq * 4);
            int kl = kq * 4;
            const float vv[4] = {v.x, v.y, v.z, v.w};
#pragma unroll
            for (int j = 0; j < 4; j++) {
                __nv_bfloat16 h = __float2bfloat16_rn(vv[j]);
                Ah[row][kl + j] = h;
                Al[row][kl + j] = __float2bfloat16_rn(vv[j] - __bfloat162float(h));
            }
        }
#pragma unroll
        for (int i = 0; i < 4; i++) {
            int idx = tid + i * 256;
            int kr = idx >> 5;
            int nq = idx & 31;
            float4 v = *(const float4*)(B + (size_t)(kt * G0_BK + kr) * G0_M + nq * 4);
            const float vv[4] = {v.x, v.y, v.z, v.w};
#pragma unroll
            for (int j = 0; j < 4; j++) {
                __nv_bfloat16 h = __float2bfloat16_rn(vv[j]);
                Bh[nq * 4 + j][kr] = h;
                Bl[nq * 4 + j][kr] = __float2bfloat16_rn(vv[j] - __bfloat162float(h));
            }
        }
        __syncthreads();

#pragma unroll
        for (int ks = 0; ks < 2; ks++) {
            const int w0 = ks * 8 + q;
            uint32_t aH[2][4], aL[2][4];
#pragma unroll
            for (int mt = 0; mt < 2; mt++) {
                int r0 = warp_m * 32 + mt * 16 + g;
                const uint32_t* ph0 = (const uint32_t*)&Ah[r0][0];
                const uint32_t* ph8 = (const uint32_t*)&Ah[r0 + 8][0];
                const uint32_t* pl0 = (const uint32_t*)&Al[r0][0];
                const uint32_t* pl8 = (const uint32_t*)&Al[r0 + 8][0];
                aH[mt][0] = ph0[w0]; aH[mt][1] = ph8[w0];
                aH[mt][2] = ph0[w0 + 4]; aH[mt][3] = ph8[w0 + 4];
                aL[mt][0] = pl0[w0]; aL[mt][1] = pl8[w0];
                aL[mt][2] = pl0[w0 + 4]; aL[mt][3] = pl8[w0 + 4];
            }
#pragma unroll
            for (int nt = 0; nt < 8; nt++) {
                int n0 = warp_n * 64 + nt * 8 + g;
                const uint32_t* pbh = (const uint32_t*)&Bh[n0][0];
                const uint32_t* pbl = (const uint32_t*)&Bl[n0][0];
                uint32_t bH0 = pbh[w0], bH1 = pbh[w0 + 4];
                uint32_t bL0 = pbl[w0], bL1 = pbl[w0 + 4];
#pragma unroll
                for (int mt = 0; mt < 2; mt++) {
                    float* c = acc[mt][nt];
                    mma_bf16(c[0], c[1], c[2], c[3],
                             aH[mt][0], aH[mt][1], aH[mt][2], aH[mt][3], bH0, bH1);
                    mma_bf16(c[0], c[1], c[2], c[3],
                             aH[mt][0], aH[mt][1], aH[mt][2], aH[mt][3], bL0, bL1);
                    mma_bf16(c[0], c[1], c[2], c[3],
                             aL[mt][0], aL[mt][1], aL[mt][2], aL[mt][3], bH0, bH1);
                }
            }
        }
        __syncthreads();
    }

    // ---- epilogue: write C rows + fused attn0 (el/er for this warp's 2 heads) ----
    // pl/pr[mt][half]: partial dots for rows (mt*16 + half*8 + g), heads warp_n*2 + {0,1}
    float pl[2][2][2], pr[2][2][2];
#pragma unroll
    for (int mt = 0; mt < 2; mt++)
#pragma unroll
        for (int hf = 0; hf < 2; hf++)
#pragma unroll
            for (int hl = 0; hl < 2; hl++) { pl[mt][hf][hl] = 0.f; pr[mt][hf][hl] = 0.f; }

#pragma unroll
    for (int mt = 0; mt < 2; mt++) {
        int r0 = rowBase + warp_m * 32 + mt * 16 + g;
        int c0 = warp_n * 64 + q * 2;
#pragma unroll
        for (int nt = 0; nt < 8; nt++) {
            float* c = acc[mt][nt];
            int col = c0 + nt * 8;          // global column = h*32+f index into al0/ar0
            int hl = nt >> 2;               // head-local (0 or 1)
            float a0c = al0[col], a1c = al0[col + 1];
            float r0c = ar0[col], r1c = ar0[col + 1];
            pl[mt][0][hl] += c[0] * a0c + c[1] * a1c;
            pr[mt][0][hl] += c[0] * r0c + c[1] * r1c;
            pl[mt][1][hl] += c[2] * a0c + c[3] * a1c;
            pr[mt][1][hl] += c[2] * r0c + c[3] * r1c;
            if (r0 < nrows)
                *(float2*)(g_z0 + (size_t)r0 * 128 + col) = make_float2(c[0], c[1]);
            if (r0 + 8 < nrows)
                *(float2*)(g_z0 + (size_t)(r0 + 8) * 128 + col) = make_float2(c[2], c[3]);
        }
    }
    // quad reduce (lanes g*4 + q, q in low 2 bits)
#pragma unroll
    for (int mt = 0; mt < 2; mt++)
#pragma unroll
        for (int hf = 0; hf < 2; hf++)
#pragma unroll
            for (int hl = 0; hl < 2; hl++) {
                float vl = pl[mt][hf][hl], vr = pr[mt][hf][hl];
                vl += __shfl_xor_sync(0xffffffffu, vl, 1);
                vl += __shfl_xor_sync(0xffffffffu, vl, 2);
                vr += __shfl_xor_sync(0xffffffffu, vr, 1);
                vr += __shfl_xor_sync(0xffffffffu, vr, 2);
                if (q == 0) {
                    int row = rowBase + warp_m * 32 + mt * 16 + hf * 8 + g;
                    if (row < nrows) {
                        int h = warp_n * 2 + hl;
                        g_el[row * 4 + h] = vl;
                        g_er[row * 4 + h] = vr;
                    }
                }
            }
}

// ================= gemm1: g_z1 = g_h0 @ W1  (+fused attn1 el/er) =================
#define G1_PAD 40
__global__ void __launch_bounds__(128) gemm1_mma_kernel(const float* __restrict__ B,
                                                        const float* __restrict__ al1,
                                                        const float* __restrict__ ar1,
                                                        int nrows) {
    __shared__ __nv_bfloat16 Ah[128][G1_PAD];
    __shared__ __nv_bfloat16 Al[128][G1_PAD];
    __shared__ __nv_bfloat16 Bh[40][G1_PAD];    // transposed [n][k]
    __shared__ __nv_bfloat16 Bl[40][G1_PAD];

    const int tid = threadIdx.x;
    const int lane = tid & 31;
    const int warp_m = tid >> 5;      // 4 warps over 128 rows
    const int rowBase = blockIdx.x * 128;
    const int g = lane >> 2;
    const int q = lane & 3;

    float acc[2][5][4];
#pragma unroll
    for (int mt = 0; mt < 2; mt++)
#pragma unroll
        for (int nt = 0; nt < 5; nt++)
#pragma unroll
            for (int i = 0; i < 4; i++) acc[mt][nt][i] = 0.f;

    for (int kt = 0; kt < 4; kt++) {           // K=128, BK=32
#pragma unroll
        for (int i = 0; i < 8; i++) {
            int idx = tid + i * 128;           // 0..1023
            int row = idx >> 3;
            int kq  = idx & 7;
            float4 v = make_float4(0.f, 0.f, 0.f, 0.f);
            if (rowBase + row < nrows)
                v = *(const float4*)(g_h0 + (size_t)(rowBase + row) * 128 + kt * 32 + kq * 4);
            int kl = kq * 4;
            const float vv[4] = {v.x, v.y, v.z, v.w};
#pragma unroll
            for (int j = 0; j < 4; j++) {
                __nv_bfloat16 h = __float2bfloat16_rn(vv[j]);
                Ah[row][kl + j] = h;
                Al[row][kl + j] = __float2bfloat16_rn(vv[j] - __bfloat162float(h));
            }
        }
#pragma unroll
        for (int i = 0; i < 10; i++) {
            int idx = tid + i * 128;           // 0..1279
            int kr = idx / 40;
            int nq = idx % 40;
            float v = B[(size_t)(kt * 32 + kr) * 40 + nq];
            __nv_bfloat16 h = __float2bfloat16_rn(v);
            Bh[nq][kr] = h;
            Bl[nq][kr] = __float2bfloat16_rn(v - __bfloat162float(h));
        }
        __syncthreads();

#pragma unroll
        for (int ks = 0; ks < 2; ks++) {
            const int w0 = ks * 8 + q;
            uint32_t aH[2][4], aL[2][4];
#pragma unroll
            for (int mt = 0; mt < 2; mt++) {
                int r0 = warp_m * 32 + mt * 16 + g;
                const uint32_t* ph0 = (const uint32_t*)&Ah[r0][0];
                const uint32_t* ph8 = (const uint32_t*)&Ah[r0 + 8][0];
                const uint32_t* pl0 = (const uint32_t*)&Al[r0][0];
                const uint32_t* pl8 = (const uint32_t*)&Al[r0 + 8][0];
                aH[mt][0] = ph0[w0]; aH[mt][1] = ph8[w0];
                aH[mt][2] = ph0[w0 + 4]; aH[mt][3] = ph8[w0 + 4];
                aL[mt][0] = pl0[w0]; aL[mt][1] = pl8[w0];
                aL[mt][2] = pl0[w0 + 4]; aL[mt][3] = pl8[w0 + 4];
            }
#pragma unroll
            for (int nt = 0; nt < 5; nt++) {
                int n0 = nt * 8 + g;
                const uint32_t* pbh = (const uint32_t*)&Bh[n0][0];
                const uint32_t* pbl = (const uint32_t*)&Bl[n0][0];
                uint32_t bH0 = pbh[w0], bH1 = pbh[w0 + 4];
                uint32_t bL0 = pbl[w0], bL1 = pbl[w0 + 4];
#pragma unroll
                for (int mt = 0; mt < 2; mt++) {
                    float* c = acc[mt][nt];
                    mma_bf16(c[0], c[1], c[2], c[3],
                             aH[mt][0], aH[mt][1], aH[mt][2], aH[mt][3], bH0, bH1);
                    mma_bf16(c[0], c[1], c[2], c[3],
                             aH[mt][0], aH[mt][1], aH[mt][2], aH[mt][3], bL0, bL1);
                    mma_bf16(c[0], c[1], c[2], c[3],
                             aL[mt][0], aL[mt][1], aL[mt][2], aL[mt][3], bH0, bH1);
                }
            }
        }
        __syncthreads();
    }

    // ---- epilogue: write z1 + fused attn1 ----
    float pl[2][2], pr[2][2];
#pragma unroll
    for (int mt = 0; mt < 2; mt++)
#pragma unroll
        for (int hf = 0; hf < 2; hf++) { pl[mt][hf] = 0.f; pr[mt][hf] = 0.f; }

#pragma unroll
    for (int mt = 0; mt < 2; mt++) {
        int r0 = rowBase + warp_m * 32 + mt * 16 + g;
#pragma unroll
        for (int nt = 0; nt < 5; nt++) {
            float* c = acc[mt][nt];
            int col = nt * 8 + q * 2;
            float a0c = al1[col], a1c = al1[col + 1];
            float r0c = ar1[col], r1c = ar1[col + 1];
            pl[mt][0] += c[0] * a0c + c[1] * a1c;
            pr[mt][0] += c[0] * r0c + c[1] * r1c;
            pl[mt][1] += c[2] * a0c + c[3] * a1c;
            pr[mt][1] += c[2] * r0c + c[3] * r1c;
            if (r0 < nrows)
                *(float2*)(g_z1 + (size_t)r0 * 40 + col) = make_float2(c[0], c[1]);
            if (r0 + 8 < nrows)
                *(float2*)(g_z1 + (size_t)(r0 + 8) * 40 + col) = make_float2(c[2], c[3]);
        }
    }
#pragma unroll
    for (int mt = 0; mt < 2; mt++)
#pragma unroll
        for (int hf = 0; hf < 2; hf++) {
            float vl = pl[mt][hf], vr = pr[mt][hf];
            vl += __shfl_xor_sync(0xffffffffu, vl, 1);
            vl += __shfl_xor_sync(0xffffffffu, vl, 2);
            vr += __shfl_xor_sync(0xffffffffu, vr, 1);
            vr += __shfl_xor_sync(0xffffffffu, vr, 2);
            if (q == 0) {
                int row = rowBase + warp_m * 32 + mt * 16 + hf * 8 + g;
                if (row < nrows) { g_el[row] = vl; g_er[row] = vr; }
            }
        }
}

// ---------------- CSR build ----------------
__global__ void csr_zero_kernel() {
    int i = blockIdx.x * blockDim.x + threadIdx.x;
    if (i < NN) g_cnt[i] = 0;
}
__global__ void csr_count_kernel(const int* __restrict__ src, const int* __restrict__ dst, int E) {
    int i = blockIdx.x * blockDim.x + threadIdx.x;
    int EP = E + NN;
    if (i >= EP) return;
    int d;
    if (i < E) {
        int s = src[i];
        d = dst[i];
        if (s == d) return;
    } else {
        d = i - E;
    }
    atomicAdd(&g_cnt[d], 1);
}
__global__ void scan1_kernel() {
    __shared__ int sh[512];
    int i = blockIdx.x * 512 + threadIdx.x;
    sh[threadIdx.x] = (i < NN) ? g_cnt[i] : 0;
    __syncthreads();
    for (int o = 256; o > 0; o >>= 1) {
        if (threadIdx.x < o) sh[threadIdx.x] += sh[threadIdx.x + o];
        __syncthreads();
    }
    if (threadIdx.x == 0) g_part[blockIdx.x] = sh[0];
}
__global__ void scan2_kernel(int nb) {
    int t = threadIdx.x;
    int lane = t & 31, w = t >> 5;
    int v = (t < nb) ? g_part[t] : 0;
    int x = v;
#pragma unroll
    for (int o = 1; o < 32; o <<= 1) {
        int y = __shfl_up_sync(0xffffffffu, x, o);
        if (lane >= o) x += y;
    }
    __shared__ int ws[4];
    if (lane == 31) ws[w] = x;
    __syncthreads();
    int add = 0;
#pragma unroll
    for (int i = 0; i < 4; i++) add += (i < w) ? ws[i] : 0;
    if (t < nb) g_part[t] = x + add - v;
}
__global__ void scan3_kernel() {
    __shared__ int sh[512];
    int i = blockIdx.x * 512 + threadIdx.x;
    int v = (i < NN) ? g_cnt[i] : 0;
    sh[threadIdx.x] = v;
    __syncthreads();
    for (int o = 1; o < 512; o <<= 1) {
        int t = (threadIdx.x >= o) ? sh[threadIdx.x - o] : 0;
        __syncthreads();
        sh[threadIdx.x] += t;
        __syncthreads();
    }
    if (i < NN) {
        int excl = sh[threadIdx.x] - v + g_part[blockIdx.x];
        g_rowptr[i] = excl;
        g_fill[i] = excl;
    }
}
__global__ void csr_scatter_kernel(const int* __restrict__ src, const int* __restrict__ dst, int E) {
    int i = blockIdx.x * blockDim.x + threadIdx.x;
    int EP = E + NN;
    if (i >= EP) return;
    int s, d;
    if (i < E) {
        s = src[i]; d = dst[i];
        if (s == d) return;
    } else {
        s = d = i - E;
    }
    int pos = atomicAdd(&g_fill[d], 1);
    g_srcs[pos] = s;
}

// ---------------- layer0 gather: warp/node, smem-staged alphas ----------------
__global__ void __launch_bounds__(256) gather0_kernel(const float* __restrict__ b0) {
    __shared__ float4 sal[8][32];
    __shared__ int    ssrc[8][32];
    int w = (blockIdx.x * blockDim.x + threadIdx.x) >> 5;
    int lane = threadIdx.x & 31;
    int wl = (threadIdx.x >> 5);
    if (w >= NN) return;
    const int beg = g_rowptr[w];
    const int deg = g_cnt[w];
    const float4 erd = *(const float4*)(g_er + w * 4);

    float m0 = -1e30f, m1 = -1e30f, m2 = -1e30f, m3 = -1e30f;
    for (int t = lane; t < deg; t += 32) {
        int s = g_srcs[beg + t];
        float4 el = *(const float4*)(g_el + s * 4);
        float e0 = el.x + erd.x; e0 = e0 > 0.f ? e0 : NEG_SLOPE * e0; m0 = fmaxf(m0, e0);
        float e1 = el.y + erd.y; e1 = e1 > 0.f ? e1 : NEG_SLOPE * e1; m1 = fmaxf(m1, e1);
        float e2 = el.z + erd.z; e2 = e2 > 0.f ? e2 : NEG_SLOPE * e2; m2 = fmaxf(m2, e2);
        float e3 = el.w + erd.w; e3 = e3 > 0.f ? e3 : NEG_SLOPE * e3; m3 = fmaxf(m3, e3);
    }
#pragma unroll
    for (int o = 16; o > 0; o >>= 1) {
        m0 = fmaxf(m0, __shfl_xor_sync(0xffffffffu, m0, o));
        m1 = fmaxf(m1, __shfl_xor_sync(0xffffffffu, m1, o));
        m2 = fmaxf(m2, __shfl_xor_sync(0xffffffffu, m2, o));
        m3 = fmaxf(m3, __shfl_xor_sync(0xffffffffu, m3, o));
    }

    float s0 = 0.f, s1 = 0.f, s2 = 0.f, s3 = 0.f;
    for (int t = lane; t < deg; t += 32) {
        int s = g_srcs[beg + t];
        float4 el = *(const float4*)(g_el + s * 4);
        float e0 = el.x + erd.x; e0 = e0 > 0.f ? e0 : NEG_SLOPE * e0;
        float e1 = el.y + erd.y; e1 = e1 > 0.f ? e1 : NEG_SLOPE * e1;
        float e2 = el.z + erd.z; e2 = e2 > 0.f ? e2 : NEG_SLOPE * e2;
        float e3 = el.w + erd.w; e3 = e3 > 0.f ? e3 : NEG_SLOPE * e3;
        s0 += __expf(e0 - m0); s1 += __expf(e1 - m1);
        s2 += __expf(e2 - m2); s3 += __expf(e3 - m3);
    }
#pragma unroll
    for (int o = 16; o > 0; o >>= 1) {
        s0 += __shfl_xor_sync(0xffffffffu, s0, o);
        s1 += __shfl_xor_sync(0xffffffffu, s1, o);
        s2 += __shfl_xor_sync(0xffffffffu, s2, o);
        s3 += __shfl_xor_sync(0xffffffffu, s3, o);
    }
    const float i0 = __frcp_rn(s0), i1 = __frcp_rn(s1), i2 = __frcp_rn(s2), i3 = __frcp_rn(s3);

    float a0 = 0.f, a1 = 0.f, a2 = 0.f, a3 = 0.f;
    for (int c0 = 0; c0 < deg; c0 += 32) {
        int t = c0 + lane;
        float4 av = make_float4(0.f, 0.f, 0.f, 0.f);
        int sidx = 0;
        if (t < deg) {
            sidx = g_srcs[beg + t];
            float4 el = *(const float4*)(g_el + sidx * 4);
            float e0 = el.x + erd.x; e0 = e0 > 0.f ? e0 : NEG_SLOPE * e0;
            float e1 = el.y + erd.y; e1 = e1 > 0.f ? e1 : NEG_SLOPE * e1;
            float e2 = el.z + erd.z; e2 = e2 > 0.f ? e2 : NEG_SLOPE * e2;
            float e3 = el.w + erd.w; e3 = e3 > 0.f ? e3 : NEG_SLOPE * e3;
            av = make_float4(__expf(e0 - m0) * i0, __expf(e1 - m1) * i1,
                             __expf(e2 - m2) * i2, __expf(e3 - m3) * i3);
        }
        sal[wl][lane] = av;
        ssrc[wl][lane] = sidx;
        __syncwarp();
        int lim = min(32, deg - c0);
        for (int j = 0; j < lim; j++) {
            float4 aj = sal[wl][j];
            const float* zr = g_z0 + (size_t)ssrc[wl][j] * 128;
            a0 = fmaf(aj.x, zr[lane],      a0);
            a1 = fmaf(aj.y, zr[32 + lane], a1);
            a2 = fmaf(aj.z, zr[64 + lane], a2);
            a3 = fmaf(aj.w, zr[96 + lane], a3);
        }
        __syncwarp();
    }
    float* hr = g_h0 + (size_t)w * 128;
    float v;
    v = a0 + b0[lane];       hr[lane]      = v > 0.f ? v : (__expf(v) - 1.f);
    v = a1 + b0[32 + lane];  hr[32 + lane] = v > 0.f ? v : (__expf(v) - 1.f);
    v = a2 + b0[64 + lane];  hr[64 + lane] = v > 0.f ? v : (__expf(v) - 1.f);
    v = a3 + b0[96 + lane];  hr[96 + lane] = v > 0.f ? v : (__expf(v) - 1.f);
}

// ---------------- layer1 gather ----------------
__global__ void __launch_bounds__(256) gather1_kernel(float* __restrict__ out,
                                                      const float* __restrict__ b1) {
    __shared__ float sal[8][32];
    __shared__ int   ssrc[8][32];
    int w = (blockIdx.x * blockDim.x + threadIdx.x) >> 5;
    int lane = threadIdx.x & 31;
    int wl = (threadIdx.x >> 5);
    if (w >= NN) return;
    const int beg = g_rowptr[w];
    const int deg = g_cnt[w];
    const float erd = g_er[w];

    float m = -1e30f;
    for (int t = lane; t < deg; t += 32) {
        int s = g_srcs[beg + t];
        float e = g_el[s] + erd; e = e > 0.f ? e : NEG_SLOPE * e;
        m = fmaxf(m, e);
    }
#pragma unroll
    for (int o = 16; o > 0; o >>= 1) m = fmaxf(m, __shfl_xor_sync(0xffffffffu, m, o));

    float ssum = 0.f;
    for (int t = lane; t < deg; t += 32) {
        int s = g_srcs[beg + t];
        float e = g_el[s] + erd; e = e > 0.f ? e : NEG_SLOPE * e;
        ssum += __expf(e - m);
    }
#pragma unroll
    for (int o = 16; o > 0; o >>= 1) ssum += __shfl_xor_sync(0xffffffffu, ssum, o);
    const float inv = __frcp_rn(ssum);

    float a0 = 0.f, a1 = 0.f;
    for (int c0 = 0; c0 < deg; c0 += 32) {
        int t = c0 + lane;
        float av = 0.f;
        int sidx = 0;
        if (t < deg) {
            sidx = g_srcs[beg + t];
            float e = g_el[sidx] + erd; e = e > 0.f ? e : NEG_SLOPE * e;
            av = __expf(e - m) * inv;
        }
        sal[wl][lane] = av;
        ssrc[wl][lane] = sidx;
        __syncwarp();
        int lim = min(32, deg - c0);
        for (int j = 0; j < lim; j++) {
            float aj = sal[wl][j];
            const float* zr = g_z1 + (size_t)ssrc[wl][j] * 40;
            a0 = fmaf(aj, zr[lane], a0);
            if (lane < 8) a1 = fmaf(aj, zr[32 + lane], a1);
        }
        __syncwarp();
    }
    float v = a0 + b1[lane];
    out[(size_t)w * 40 + lane] = v > 0.f ? v : (__expf(v) - 1.f);
    if (lane < 8) {
        v = a1 + b1[32 + lane];
        out[(size_t)w * 40 + 32 + lane] = v > 0.f ? v : (__expf(v) - 1.f);
    }
}

// ---------------- launch ----------------
extern "C" void kernel_launch(void* const* d_in, const int* in_sizes, int n_in,
                              void* d_out, int out_size) {
    const float* x   = (const float*)d_in[0];
    const int*   src = (const int*)d_in[1];
    const int*   dst = (const int*)d_in[2];
    const float* W0  = (const float*)d_in[3];
    const float* al0 = (const float*)d_in[4];
    const float* ar0 = (const float*)d_in[5];
    const float* b0  = (const float*)d_in[6];
    const float* W1  = (const float*)d_in[7];
    const float* al1 = (const float*)d_in[8];
    const float* ar1 = (const float*)d_in[9];
    const float* b1  = (const float*)d_in[10];
    float* out = (float*)d_out;

    const int E  = in_sizes[1];
    const int EP = E + NN;

    // launch order puts gemm0_mma at index 5 (ncu captures -s 5 -c 1)
    csr_zero_kernel<<<(NN + 255) / 256, 256>>>();                     // 0
    csr_count_kernel<<<(EP + 255) / 256, 256>>>(src, dst, E);         // 1
    scan1_kernel<<<NB_SCAN, 512>>>();                                 // 2
    scan2_kernel<<<1, 128>>>(NB_SCAN);                                // 3
    scan3_kernel<<<NB_SCAN, 512>>>();                                 // 4
    gemm0_mma_kernel<<<(NN + 127) / 128, 256>>>(x, W0, al0, ar0, NN); // 5  <- profiled
    csr_scatter_kernel<<<(EP + 255) / 256, 256>>>(src, dst, E);       // 6
    gather0_kernel<<<(NN * 32 + 255) / 256, 256>>>(b0);               // 7
    gemm1_mma_kernel<<<(NN + 127) / 128, 128>>>(W1, al1, ar1, NN);    // 8
    gather1_kernel<<<(NN * 32 + 255) / 256, 256>>>(out, b1);          // 9
}